// round 1
// baseline (speedup 1.0000x reference)
#include <cuda_runtime.h>

#define D_MODEL   768
#define KV_DIM    1536
#define NUM_HEADS 12
#define HEAD_DIM  64
#define BATCH     4
#define SEQ       2048
#define M_TOT     (BATCH * SEQ)   // 8192

// Scratch (no allocations allowed anywhere)
__device__ float g_q[M_TOT * D_MODEL];     // [B*S, 768]   Q projection
__device__ float g_kv[M_TOT * KV_DIM];     // [B*S, 1536]  KV projection
__device__ float g_attn[M_TOT * D_MODEL];  // [B*S, 768]   attention output

// ---------------------------------------------------------------------------
// GEMM: C[m][n] = sum_k A[m][k] * W[n][k] + bias[n]
// A: [M,K] row-major, W: [N,K] row-major (i.e. C = A @ W^T + b)
// Tiles 64x64x16, 256 threads, 4x4 per-thread micro-tile.
// Shared tiles stored K-major-transposed ([BK][BM+4]) so compute-phase
// fragment loads are LDS.128 and conflict-free.
// ---------------------------------------------------------------------------
#define BM 64
#define BN 64
#define BK 16

__global__ __launch_bounds__(256, 2)
void gemm_bias_kernel(const float* __restrict__ A, const float* __restrict__ W,
                      const float* __restrict__ bias, float* __restrict__ C,
                      int M, int N, int K)
{
    __shared__ float As[BK][BM + 4];
    __shared__ float Ws[BK][BN + 4];

    const int tid  = threadIdx.x;
    const int tx   = tid & 15;        // 16 col-groups
    const int ty   = tid >> 4;        // 16 row-groups
    const int lrow = tid >> 2;        // 0..63  (load row)
    const int lc4  = (tid & 3) << 2;  // 0,4,8,12 (load k-offset)

    const float* Ab = A + (size_t)(blockIdx.y * BM) * K;
    const float* Wb = W + (size_t)(blockIdx.x * BN) * K;

    float acc[4][4] = {};

    for (int k0 = 0; k0 < K; k0 += BK) {
        float4 av = *(const float4*)(Ab + (size_t)lrow * K + k0 + lc4);
        float4 wv = *(const float4*)(Wb + (size_t)lrow * K + k0 + lc4);
        As[lc4 + 0][lrow] = av.x; As[lc4 + 1][lrow] = av.y;
        As[lc4 + 2][lrow] = av.z; As[lc4 + 3][lrow] = av.w;
        Ws[lc4 + 0][lrow] = wv.x; Ws[lc4 + 1][lrow] = wv.y;
        Ws[lc4 + 2][lrow] = wv.z; Ws[lc4 + 3][lrow] = wv.w;
        __syncthreads();

        #pragma unroll
        for (int k = 0; k < BK; k++) {
            float4 a = *(const float4*)&As[k][ty << 2];
            float4 w = *(const float4*)&Ws[k][tx << 2];
            float a4[4] = {a.x, a.y, a.z, a.w};
            float w4[4] = {w.x, w.y, w.z, w.w};
            #pragma unroll
            for (int i = 0; i < 4; i++)
                #pragma unroll
                for (int j = 0; j < 4; j++)
                    acc[i][j] = fmaf(a4[i], w4[j], acc[i][j]);
        }
        __syncthreads();
    }

    const int row0 = blockIdx.y * BM + (ty << 2);
    const int col0 = blockIdx.x * BN + (tx << 2);
    float4 bv = *(const float4*)(bias + col0);
    #pragma unroll
    for (int i = 0; i < 4; i++) {
        float4 r;
        r.x = acc[i][0] + bv.x;
        r.y = acc[i][1] + bv.y;
        r.z = acc[i][2] + bv.z;
        r.w = acc[i][3] + bv.w;
        *(float4*)(C + (size_t)(row0 + i) * N + col0) = r;
    }
}

// ---------------------------------------------------------------------------
// Flash attention (fp32, online softmax).
// Grid: (S/64, H, B). Block: 256 threads. One 64-query tile per block.
// Q pre-scaled by 1/sqrt(Dh). K stored d-major transposed for the S GEMM,
// V row-major for the P@V GEMM, P staged through smem.
// ---------------------------------------------------------------------------
#define AQ  64
#define AK  64
#define LDP 68                       // padded leading dim (floats)
#define ATTN_SMEM_BYTES (4 * 64 * LDP * 4)   // QT,KT,VS,PS = 69632 B

__global__ __launch_bounds__(256, 1)
void attn_kernel(const float* __restrict__ q, const float* __restrict__ kv,
                 const float* __restrict__ mask, float* __restrict__ outp)
{
    extern __shared__ float sm[];
    float* QT = sm;                  // [d][q]  64 x LDP (transposed, scaled)
    float* KT = sm + 64 * LDP;       // [d][k]  64 x LDP (transposed)
    float* VS = sm + 2 * 64 * LDP;   // [k][d]  64 x LDP (row-major)
    float* PS = sm + 3 * 64 * LDP;   // [q][k]  64 x LDP

    const int qt  = blockIdx.x;
    const int h   = blockIdx.y;
    const int b   = blockIdx.z;
    const int tid = threadIdx.x;
    const int tx  = tid & 15;
    const int ty  = tid >> 4;

    // ---- Load Q tile (transposed + pre-scaled by 1/sqrt(64)) ----
    {
        const float* qbase = q + (size_t)(b * SEQ + qt * AQ) * D_MODEL + h * HEAD_DIM;
        #pragma unroll
        for (int r = 0; r < 4; r++) {
            int idx = tid + r * 256;
            int row = idx >> 4;
            int d4  = (idx & 15) << 2;
            float4 v = *(const float4*)(qbase + (size_t)row * D_MODEL + d4);
            QT[(d4 + 0) * LDP + row] = v.x * 0.125f;
            QT[(d4 + 1) * LDP + row] = v.y * 0.125f;
            QT[(d4 + 2) * LDP + row] = v.z * 0.125f;
            QT[(d4 + 3) * LDP + row] = v.w * 0.125f;
        }
    }

    float m_r[4], l_r[4], o[4][4];
    #pragma unroll
    for (int i = 0; i < 4; i++) {
        m_r[i] = -1e30f; l_r[i] = 0.0f;
        #pragma unroll
        for (int j = 0; j < 4; j++) o[i][j] = 0.0f;
    }

    const float* kbase0   = kv + (size_t)(b * SEQ) * KV_DIM + h * (2 * HEAD_DIM);
    const float* maskbase = mask + (size_t)(qt * AQ) * SEQ;

    for (int kt = 0; kt < SEQ / AK; kt++) {
        // ---- Load K (transposed) and V (row-major) tiles ----
        const float* kb = kbase0 + (size_t)(kt * AK) * KV_DIM;
        #pragma unroll
        for (int r = 0; r < 4; r++) {
            int idx = tid + r * 256;
            int row = idx >> 4;
            int d4  = (idx & 15) << 2;
            float4 kvv = *(const float4*)(kb + (size_t)row * KV_DIM + d4);
            KT[(d4 + 0) * LDP + row] = kvv.x;
            KT[(d4 + 1) * LDP + row] = kvv.y;
            KT[(d4 + 2) * LDP + row] = kvv.z;
            KT[(d4 + 3) * LDP + row] = kvv.w;
            float4 vv = *(const float4*)(kb + (size_t)row * KV_DIM + HEAD_DIM + d4);
            *(float4*)&VS[row * LDP + d4] = vv;
        }
        __syncthreads();

        // ---- S = Q K^T (scaled) ----
        float s[4][4] = {};
        #pragma unroll 16
        for (int d = 0; d < HEAD_DIM; d++) {
            float4 qv = *(const float4*)&QT[d * LDP + (ty << 2)];
            float4 kf = *(const float4*)&KT[d * LDP + (tx << 2)];
            float qa[4] = {qv.x, qv.y, qv.z, qv.w};
            float ka[4] = {kf.x, kf.y, kf.z, kf.w};
            #pragma unroll
            for (int i = 0; i < 4; i++)
                #pragma unroll
                for (int j = 0; j < 4; j++)
                    s[i][j] = fmaf(qa[i], ka[j], s[i][j]);
        }

        // ---- mask + online softmax update ----
        #pragma unroll
        for (int i = 0; i < 4; i++) {
            float4 mv = *(const float4*)(maskbase + (size_t)(ty * 4 + i) * SEQ
                                         + kt * AK + (tx << 2));
            s[i][0] += mv.x; s[i][1] += mv.y; s[i][2] += mv.z; s[i][3] += mv.w;

            float mx = fmaxf(fmaxf(s[i][0], s[i][1]), fmaxf(s[i][2], s[i][3]));
            mx = fmaxf(mx, __shfl_xor_sync(0xffffffffu, mx, 1));
            mx = fmaxf(mx, __shfl_xor_sync(0xffffffffu, mx, 2));
            mx = fmaxf(mx, __shfl_xor_sync(0xffffffffu, mx, 4));
            mx = fmaxf(mx, __shfl_xor_sync(0xffffffffu, mx, 8));
            float nm = fmaxf(m_r[i], mx);

            float p0 = __expf(s[i][0] - nm);
            float p1 = __expf(s[i][1] - nm);
            float p2 = __expf(s[i][2] - nm);
            float p3 = __expf(s[i][3] - nm);
            float rs = p0 + p1 + p2 + p3;
            rs += __shfl_xor_sync(0xffffffffu, rs, 1);
            rs += __shfl_xor_sync(0xffffffffu, rs, 2);
            rs += __shfl_xor_sync(0xffffffffu, rs, 4);
            rs += __shfl_xor_sync(0xffffffffu, rs, 8);

            float sc = __expf(m_r[i] - nm);
            l_r[i] = l_r[i] * sc + rs;
            m_r[i] = nm;
            o[i][0] *= sc; o[i][1] *= sc; o[i][2] *= sc; o[i][3] *= sc;

            float4 pv = make_float4(p0, p1, p2, p3);
            *(float4*)&PS[(ty * 4 + i) * LDP + (tx << 2)] = pv;
        }
        __syncthreads();

        // ---- O += P V ----
        #pragma unroll 16
        for (int k = 0; k < AK; k++) {
            float4 vv = *(const float4*)&VS[k * LDP + (tx << 2)];
            #pragma unroll
            for (int i = 0; i < 4; i++) {
                float p = PS[(ty * 4 + i) * LDP + k];
                o[i][0] = fmaf(p, vv.x, o[i][0]);
                o[i][1] = fmaf(p, vv.y, o[i][1]);
                o[i][2] = fmaf(p, vv.z, o[i][2]);
                o[i][3] = fmaf(p, vv.w, o[i][3]);
            }
        }
        __syncthreads();
    }

    // ---- normalize + write [B*S, 768] layout (head-interleaved) ----
    #pragma unroll
    for (int i = 0; i < 4; i++) {
        float inv = 1.0f / l_r[i];
        size_t row = (size_t)(b * SEQ + qt * AQ + ty * 4 + i);
        float4 r = make_float4(o[i][0] * inv, o[i][1] * inv,
                               o[i][2] * inv, o[i][3] * inv);
        *(float4*)(outp + row * D_MODEL + h * HEAD_DIM + (tx << 2)) = r;
    }
}

// ---------------------------------------------------------------------------
extern "C" void kernel_launch(void* const* d_in, const int* in_sizes, int n_in,
                              void* d_out, int out_size)
{
    const float* x    = (const float*)d_in[0];
    const float* y    = (const float*)d_in[1];
    const float* mask = (const float*)d_in[2];
    const float* Wq   = (const float*)d_in[3];
    const float* bq   = (const float*)d_in[4];
    const float* Wkv  = (const float*)d_in[5];
    const float* bkv  = (const float*)d_in[6];
    const float* Wo   = (const float*)d_in[7];
    const float* bo   = (const float*)d_in[8];
    float* out = (float*)d_out;

    float *qp, *kvp, *attnp;
    cudaGetSymbolAddress((void**)&qp,    g_q);
    cudaGetSymbolAddress((void**)&kvp,   g_kv);
    cudaGetSymbolAddress((void**)&attnp, g_attn);

    cudaFuncSetAttribute(attn_kernel,
                         cudaFuncAttributeMaxDynamicSharedMemorySize,
                         ATTN_SMEM_BYTES);

    dim3 blk(256);

    // Q = x @ Wq^T + bq
    gemm_bias_kernel<<<dim3(D_MODEL / BN, M_TOT / BM), blk>>>(
        x, Wq, bq, qp, M_TOT, D_MODEL, D_MODEL);
    // KV = y @ Wkv^T + bkv
    gemm_bias_kernel<<<dim3(KV_DIM / BN, M_TOT / BM), blk>>>(
        y, Wkv, bkv, kvp, M_TOT, KV_DIM, D_MODEL);
    // attention
    attn_kernel<<<dim3(SEQ / AQ, NUM_HEADS, BATCH), blk, ATTN_SMEM_BYTES>>>(
        qp, kvp, mask, attnp);
    // out = attn @ Wo^T + bo
    gemm_bias_kernel<<<dim3(D_MODEL / BN, M_TOT / BM), blk>>>(
        attnp, Wo, bo, out, M_TOT, D_MODEL, D_MODEL);
}

// round 2
// speedup vs baseline: 1.4036x; 1.4036x over previous
#include <cuda_runtime.h>

#define D_MODEL   768
#define KV_DIM    1536
#define NUM_HEADS 12
#define HEAD_DIM  64
#define BATCH     4
#define SEQ       2048
#define M_TOT     (BATCH * SEQ)   // 8192

// Scratch (no allocations allowed anywhere)
__device__ float g_q[M_TOT * D_MODEL];     // [B*S, 768]   Q projection
__device__ float g_kv[M_TOT * KV_DIM];     // [B*S, 1536]  KV projection
__device__ float g_attn[M_TOT * D_MODEL];  // [B*S, 768]   attention output

// ---------------------------------------------------------------------------
// tf32 helpers
// ---------------------------------------------------------------------------
__device__ __forceinline__ unsigned f2tf(float f) {
    unsigned r;
    asm("cvt.rna.tf32.f32 %0, %1;" : "=r"(r) : "f"(f));
    return r;
}

__device__ __forceinline__ void mma_tf32(float c[4],
                                         unsigned a0, unsigned a1,
                                         unsigned a2, unsigned a3,
                                         unsigned b0, unsigned b1)
{
    asm("mma.sync.aligned.m16n8k8.row.col.f32.tf32.tf32.f32 "
        "{%0,%1,%2,%3}, {%4,%5,%6,%7}, {%8,%9}, {%0,%1,%2,%3};\n"
        : "+f"(c[0]), "+f"(c[1]), "+f"(c[2]), "+f"(c[3])
        : "r"(a0), "r"(a1), "r"(a2), "r"(a3), "r"(b0), "r"(b1));
}

// ---------------------------------------------------------------------------
// Tensor-core GEMM: C[m][n] = sum_k A[m][k]*W[n][k] + bias[n]   (C = A @ W^T + b)
// Block tile 128x128x32, 256 threads (8 warps), warp tile 64x32.
// Fragments are pre-permuted into smem at load time so compute-phase reads
// are conflict-free LDS.128 (A) / LDS.64 (B).
//
// A smem element (within 16x8 mma tile): lane=(r%8)*4+(c%4),
//   slot = (r>=8) | ((c>=4)<<1)  -> exactly the m16n8k8 tf32 A fragment order.
// B smem element (8x8 k x n tile): lane=(n%8)*4+(k%4), slot=(k>=4).
// ---------------------------------------------------------------------------
#define AS_KSTRIDE 1032   // (8 mtiles * 32 lanes * 4 slots) + 8 pad floats
#define BS_KSTRIDE 1028   // (16 ntiles * 32 lanes * 2 slots) + 4 pad floats

__global__ __launch_bounds__(256, 2)
void gemm_tf32_kernel(const float* __restrict__ A, const float* __restrict__ W,
                      const float* __restrict__ bias, float* __restrict__ C,
                      int M, int N, int K)
{
    __shared__ __align__(16) float As[4][AS_KSTRIDE];
    __shared__ __align__(16) float Bs[4][BS_KSTRIDE];

    const int tid  = threadIdx.x;
    const int lane = tid & 31;
    const int warp = tid >> 5;
    const int wm   = warp & 1;    // m half (0..1)
    const int wn   = warp >> 1;   // n quarter (0..3)

    const float* Ab = A + (size_t)(blockIdx.y * 128) * K;
    const float* Wb = W + (size_t)(blockIdx.x * 128) * K;

    float acc[4][4][4];
    #pragma unroll
    for (int i = 0; i < 4; i++)
        #pragma unroll
        for (int j = 0; j < 4; j++)
            #pragma unroll
            for (int r = 0; r < 4; r++) acc[i][j][r] = 0.0f;

    for (int k0 = 0; k0 < K; k0 += 32) {
        // ---- load + permute A tile (128x32) ----
        #pragma unroll
        for (int i = 0; i < 4; i++) {
            int idx = tid + i * 256;
            int row = idx >> 3;             // 0..127
            int c0  = (idx & 7) << 2;       // 0..28 step 4
            float4 v = *(const float4*)(Ab + (size_t)row * K + k0 + c0);
            int kk   = c0 >> 3;
            int cc   = c0 & 7;              // 0 or 4
            int mt   = row >> 4;
            int rr   = row & 15;
            int slot = (rr >> 3) | ((cc >> 2) << 1);
            int base = (mt * 32 + ((rr & 7) << 2)) * 4 + slot;
            As[kk][base +  0] = __uint_as_float(f2tf(v.x));
            As[kk][base +  4] = __uint_as_float(f2tf(v.y));
            As[kk][base +  8] = __uint_as_float(f2tf(v.z));
            As[kk][base + 12] = __uint_as_float(f2tf(v.w));
        }
        // ---- load + permute B tile (W rows: 128 x 32) ----
        #pragma unroll
        for (int i = 0; i < 4; i++) {
            int idx = tid + i * 256;
            int n   = idx >> 3;             // 0..127
            int c0  = (idx & 7) << 2;
            float4 v = *(const float4*)(Wb + (size_t)n * K + k0 + c0);
            int kk   = c0 >> 3;
            int cc   = c0 & 7;
            int nt   = n >> 3;
            int nn   = n & 7;
            int slot = cc >> 2;
            int base = (nt * 32 + (nn << 2)) * 2 + slot;
            Bs[kk][base + 0] = __uint_as_float(f2tf(v.x));
            Bs[kk][base + 2] = __uint_as_float(f2tf(v.y));
            Bs[kk][base + 4] = __uint_as_float(f2tf(v.z));
            Bs[kk][base + 6] = __uint_as_float(f2tf(v.w));
        }
        __syncthreads();

        // ---- compute: 4 k-steps of 8, per warp 4x4 mma tiles ----
        #pragma unroll
        for (int kk = 0; kk < 4; kk++) {
            unsigned a[4][4], b[4][2];
            #pragma unroll
            for (int mt = 0; mt < 4; mt++) {
                float4 av = *(const float4*)&As[kk][((wm * 4 + mt) * 32 + lane) * 4];
                a[mt][0] = __float_as_uint(av.x);
                a[mt][1] = __float_as_uint(av.y);
                a[mt][2] = __float_as_uint(av.z);
                a[mt][3] = __float_as_uint(av.w);
            }
            #pragma unroll
            for (int nt = 0; nt < 4; nt++) {
                float2 bv = *(const float2*)&Bs[kk][((wn * 4 + nt) * 32 + lane) * 2];
                b[nt][0] = __float_as_uint(bv.x);
                b[nt][1] = __float_as_uint(bv.y);
            }
            #pragma unroll
            for (int mt = 0; mt < 4; mt++)
                #pragma unroll
                for (int nt = 0; nt < 4; nt++)
                    mma_tf32(acc[mt][nt], a[mt][0], a[mt][1], a[mt][2], a[mt][3],
                             b[nt][0], b[nt][1]);
        }
        __syncthreads();
    }

    // ---- epilogue: bias + store ----
    #pragma unroll
    for (int mt = 0; mt < 4; mt++) {
        int row = blockIdx.y * 128 + (wm * 4 + mt) * 16 + (lane >> 2);
        #pragma unroll
        for (int nt = 0; nt < 4; nt++) {
            int col = blockIdx.x * 128 + (wn * 4 + nt) * 8 + ((lane & 3) << 1);
            float2 bv = *(const float2*)(bias + col);
            float2 r0, r1;
            r0.x = acc[mt][nt][0] + bv.x;
            r0.y = acc[mt][nt][1] + bv.y;
            r1.x = acc[mt][nt][2] + bv.x;
            r1.y = acc[mt][nt][3] + bv.y;
            *(float2*)(C + (size_t)row * N + col)       = r0;
            *(float2*)(C + (size_t)(row + 8) * N + col) = r1;
        }
    }
}

// ---------------------------------------------------------------------------
// Flash attention (fp32, online softmax). Unchanged except occupancy hint.
// Grid: (S/64, H, B). Block: 256 threads. One 64-query tile per block.
// ---------------------------------------------------------------------------
#define AQ  64
#define AK  64
#define LDP 68                       // padded leading dim (floats)
#define ATTN_SMEM_BYTES (4 * 64 * LDP * 4)   // QT,KT,VS,PS = 69632 B

__global__ __launch_bounds__(256, 2)
void attn_kernel(const float* __restrict__ q, const float* __restrict__ kv,
                 const float* __restrict__ mask, float* __restrict__ outp)
{
    extern __shared__ float sm[];
    float* QT = sm;                  // [d][q]  64 x LDP (transposed, scaled)
    float* KT = sm + 64 * LDP;       // [d][k]  64 x LDP (transposed)
    float* VS = sm + 2 * 64 * LDP;   // [k][d]  64 x LDP (row-major)
    float* PS = sm + 3 * 64 * LDP;   // [q][k]  64 x LDP

    const int qt  = blockIdx.x;
    const int h   = blockIdx.y;
    const int b   = blockIdx.z;
    const int tid = threadIdx.x;
    const int tx  = tid & 15;
    const int ty  = tid >> 4;

    // ---- Load Q tile (transposed + pre-scaled by 1/sqrt(64)) ----
    {
        const float* qbase = q + (size_t)(b * SEQ + qt * AQ) * D_MODEL + h * HEAD_DIM;
        #pragma unroll
        for (int r = 0; r < 4; r++) {
            int idx = tid + r * 256;
            int row = idx >> 4;
            int d4  = (idx & 15) << 2;
            float4 v = *(const float4*)(qbase + (size_t)row * D_MODEL + d4);
            QT[(d4 + 0) * LDP + row] = v.x * 0.125f;
            QT[(d4 + 1) * LDP + row] = v.y * 0.125f;
            QT[(d4 + 2) * LDP + row] = v.z * 0.125f;
            QT[(d4 + 3) * LDP + row] = v.w * 0.125f;
        }
    }

    float m_r[4], l_r[4], o[4][4];
    #pragma unroll
    for (int i = 0; i < 4; i++) {
        m_r[i] = -1e30f; l_r[i] = 0.0f;
        #pragma unroll
        for (int j = 0; j < 4; j++) o[i][j] = 0.0f;
    }

    const float* kbase0   = kv + (size_t)(b * SEQ) * KV_DIM + h * (2 * HEAD_DIM);
    const float* maskbase = mask + (size_t)(qt * AQ) * SEQ;

    for (int kt = 0; kt < SEQ / AK; kt++) {
        // ---- Load K (transposed) and V (row-major) tiles ----
        const float* kb = kbase0 + (size_t)(kt * AK) * KV_DIM;
        #pragma unroll
        for (int r = 0; r < 4; r++) {
            int idx = tid + r * 256;
            int row = idx >> 4;
            int d4  = (idx & 15) << 2;
            float4 kvv = *(const float4*)(kb + (size_t)row * KV_DIM + d4);
            KT[(d4 + 0) * LDP + row] = kvv.x;
            KT[(d4 + 1) * LDP + row] = kvv.y;
            KT[(d4 + 2) * LDP + row] = kvv.z;
            KT[(d4 + 3) * LDP + row] = kvv.w;
            float4 vv = *(const float4*)(kb + (size_t)row * KV_DIM + HEAD_DIM + d4);
            *(float4*)&VS[row * LDP + d4] = vv;
        }
        __syncthreads();

        // ---- S = Q K^T (scaled) ----
        float s[4][4] = {};
        #pragma unroll 16
        for (int d = 0; d < HEAD_DIM; d++) {
            float4 qv = *(const float4*)&QT[d * LDP + (ty << 2)];
            float4 kf = *(const float4*)&KT[d * LDP + (tx << 2)];
            float qa[4] = {qv.x, qv.y, qv.z, qv.w};
            float ka[4] = {kf.x, kf.y, kf.z, kf.w};
            #pragma unroll
            for (int i = 0; i < 4; i++)
                #pragma unroll
                for (int j = 0; j < 4; j++)
                    s[i][j] = fmaf(qa[i], ka[j], s[i][j]);
        }

        // ---- mask + online softmax update ----
        #pragma unroll
        for (int i = 0; i < 4; i++) {
            float4 mv = *(const float4*)(maskbase + (size_t)(ty * 4 + i) * SEQ
                                         + kt * AK + (tx << 2));
            s[i][0] += mv.x; s[i][1] += mv.y; s[i][2] += mv.z; s[i][3] += mv.w;

            float mx = fmaxf(fmaxf(s[i][0], s[i][1]), fmaxf(s[i][2], s[i][3]));
            mx = fmaxf(mx, __shfl_xor_sync(0xffffffffu, mx, 1));
            mx = fmaxf(mx, __shfl_xor_sync(0xffffffffu, mx, 2));
            mx = fmaxf(mx, __shfl_xor_sync(0xffffffffu, mx, 4));
            mx = fmaxf(mx, __shfl_xor_sync(0xffffffffu, mx, 8));
            float nm = fmaxf(m_r[i], mx);

            float p0 = __expf(s[i][0] - nm);
            float p1 = __expf(s[i][1] - nm);
            float p2 = __expf(s[i][2] - nm);
            float p3 = __expf(s[i][3] - nm);
            float rs = p0 + p1 + p2 + p3;
            rs += __shfl_xor_sync(0xffffffffu, rs, 1);
            rs += __shfl_xor_sync(0xffffffffu, rs, 2);
            rs += __shfl_xor_sync(0xffffffffu, rs, 4);
            rs += __shfl_xor_sync(0xffffffffu, rs, 8);

            float sc = __expf(m_r[i] - nm);
            l_r[i] = l_r[i] * sc + rs;
            m_r[i] = nm;
            o[i][0] *= sc; o[i][1] *= sc; o[i][2] *= sc; o[i][3] *= sc;

            float4 pv = make_float4(p0, p1, p2, p3);
            *(float4*)&PS[(ty * 4 + i) * LDP + (tx << 2)] = pv;
        }
        __syncthreads();

        // ---- O += P V ----
        #pragma unroll 16
        for (int k = 0; k < AK; k++) {
            float4 vv = *(const float4*)&VS[k * LDP + (tx << 2)];
            #pragma unroll
            for (int i = 0; i < 4; i++) {
                float p = PS[(ty * 4 + i) * LDP + k];
                o[i][0] = fmaf(p, vv.x, o[i][0]);
                o[i][1] = fmaf(p, vv.y, o[i][1]);
                o[i][2] = fmaf(p, vv.z, o[i][2]);
                o[i][3] = fmaf(p, vv.w, o[i][3]);
            }
        }
        __syncthreads();
    }

    // ---- normalize + write [B*S, 768] layout (head-interleaved) ----
    #pragma unroll
    for (int i = 0; i < 4; i++) {
        float inv = 1.0f / l_r[i];
        size_t row = (size_t)(b * SEQ + qt * AQ + ty * 4 + i);
        float4 r = make_float4(o[i][0] * inv, o[i][1] * inv,
                               o[i][2] * inv, o[i][3] * inv);
        *(float4*)(outp + row * D_MODEL + h * HEAD_DIM + (tx << 2)) = r;
    }
}

// ---------------------------------------------------------------------------
extern "C" void kernel_launch(void* const* d_in, const int* in_sizes, int n_in,
                              void* d_out, int out_size)
{
    const float* x    = (const float*)d_in[0];
    const float* y    = (const float*)d_in[1];
    const float* mask = (const float*)d_in[2];
    const float* Wq   = (const float*)d_in[3];
    const float* bq   = (const float*)d_in[4];
    const float* Wkv  = (const float*)d_in[5];
    const float* bkv  = (const float*)d_in[6];
    const float* Wo   = (const float*)d_in[7];
    const float* bo   = (const float*)d_in[8];
    float* out = (float*)d_out;

    float *qp, *kvp, *attnp;
    cudaGetSymbolAddress((void**)&qp,    g_q);
    cudaGetSymbolAddress((void**)&kvp,   g_kv);
    cudaGetSymbolAddress((void**)&attnp, g_attn);

    cudaFuncSetAttribute(attn_kernel,
                         cudaFuncAttributeMaxDynamicSharedMemorySize,
                         ATTN_SMEM_BYTES);

    dim3 blk(256);

    // Q = x @ Wq^T + bq
    gemm_tf32_kernel<<<dim3(D_MODEL / 128, M_TOT / 128), blk>>>(
        x, Wq, bq, qp, M_TOT, D_MODEL, D_MODEL);
    // KV = y @ Wkv^T + bkv
    gemm_tf32_kernel<<<dim3(KV_DIM / 128, M_TOT / 128), blk>>>(
        y, Wkv, bkv, kvp, M_TOT, KV_DIM, D_MODEL);
    // attention
    attn_kernel<<<dim3(SEQ / AQ, NUM_HEADS, BATCH), blk, ATTN_SMEM_BYTES>>>(
        qp, kvp, mask, attnp);
    // out = attn @ Wo^T + bo
    gemm_tf32_kernel<<<dim3(D_MODEL / 128, M_TOT / 128), blk>>>(
        attnp, Wo, bo, out, M_TOT, D_MODEL, D_MODEL);
}

// round 3
// speedup vs baseline: 2.7883x; 1.9865x over previous
#include <cuda_runtime.h>

#define D_MODEL   768
#define KV_DIM    1536
#define NUM_HEADS 12
#define HEAD_DIM  64
#define BATCH     4
#define SEQ       2048
#define M_TOT     (BATCH * SEQ)   // 8192

// Scratch (no allocations allowed anywhere)
__device__ float g_q[M_TOT * D_MODEL];     // [B*S, 768]   Q projection
__device__ float g_kv[M_TOT * KV_DIM];     // [B*S, 1536]  KV projection
__device__ float g_attn[M_TOT * D_MODEL];  // [B*S, 768]   attention output

// ---------------------------------------------------------------------------
// tf32 helpers
// ---------------------------------------------------------------------------
__device__ __forceinline__ unsigned f2tf(float f) {
    unsigned r;
    asm("cvt.rna.tf32.f32 %0, %1;" : "=r"(r) : "f"(f));
    return r;
}
__device__ __forceinline__ float f2tff(float f) {
    return __uint_as_float(f2tf(f));
}

__device__ __forceinline__ void mma_tf32(float c[4],
                                         unsigned a0, unsigned a1,
                                         unsigned a2, unsigned a3,
                                         unsigned b0, unsigned b1)
{
    asm("mma.sync.aligned.m16n8k8.row.col.f32.tf32.tf32.f32 "
        "{%0,%1,%2,%3}, {%4,%5,%6,%7}, {%8,%9}, {%0,%1,%2,%3};\n"
        : "+f"(c[0]), "+f"(c[1]), "+f"(c[2]), "+f"(c[3])
        : "r"(a0), "r"(a1), "r"(a2), "r"(a3), "r"(b0), "r"(b1));
}

// ---------------------------------------------------------------------------
// Tensor-core GEMM: C = A @ W^T + bias (unchanged from round 2)
// ---------------------------------------------------------------------------
#define AS_KSTRIDE 1032
#define BS_KSTRIDE 1028

__global__ __launch_bounds__(256, 2)
void gemm_tf32_kernel(const float* __restrict__ A, const float* __restrict__ W,
                      const float* __restrict__ bias, float* __restrict__ C,
                      int M, int N, int K)
{
    __shared__ __align__(16) float As[4][AS_KSTRIDE];
    __shared__ __align__(16) float Bs[4][BS_KSTRIDE];

    const int tid  = threadIdx.x;
    const int lane = tid & 31;
    const int warp = tid >> 5;
    const int wm   = warp & 1;
    const int wn   = warp >> 1;

    const float* Ab = A + (size_t)(blockIdx.y * 128) * K;
    const float* Wb = W + (size_t)(blockIdx.x * 128) * K;

    float acc[4][4][4];
    #pragma unroll
    for (int i = 0; i < 4; i++)
        #pragma unroll
        for (int j = 0; j < 4; j++)
            #pragma unroll
            for (int r = 0; r < 4; r++) acc[i][j][r] = 0.0f;

    for (int k0 = 0; k0 < K; k0 += 32) {
        #pragma unroll
        for (int i = 0; i < 4; i++) {
            int idx = tid + i * 256;
            int row = idx >> 3;
            int c0  = (idx & 7) << 2;
            float4 v = *(const float4*)(Ab + (size_t)row * K + k0 + c0);
            int kk   = c0 >> 3;
            int cc   = c0 & 7;
            int mt   = row >> 4;
            int rr   = row & 15;
            int slot = (rr >> 3) | ((cc >> 2) << 1);
            int base = (mt * 32 + ((rr & 7) << 2)) * 4 + slot;
            As[kk][base +  0] = f2tff(v.x);
            As[kk][base +  4] = f2tff(v.y);
            As[kk][base +  8] = f2tff(v.z);
            As[kk][base + 12] = f2tff(v.w);
        }
        #pragma unroll
        for (int i = 0; i < 4; i++) {
            int idx = tid + i * 256;
            int n   = idx >> 3;
            int c0  = (idx & 7) << 2;
            float4 v = *(const float4*)(Wb + (size_t)n * K + k0 + c0);
            int kk   = c0 >> 3;
            int cc   = c0 & 7;
            int nt   = n >> 3;
            int nn   = n & 7;
            int slot = cc >> 2;
            int base = (nt * 32 + (nn << 2)) * 2 + slot;
            Bs[kk][base + 0] = f2tff(v.x);
            Bs[kk][base + 2] = f2tff(v.y);
            Bs[kk][base + 4] = f2tff(v.z);
            Bs[kk][base + 6] = f2tff(v.w);
        }
        __syncthreads();

        #pragma unroll
        for (int kk = 0; kk < 4; kk++) {
            unsigned a[4][4], b[4][2];
            #pragma unroll
            for (int mt = 0; mt < 4; mt++) {
                float4 av = *(const float4*)&As[kk][((wm * 4 + mt) * 32 + lane) * 4];
                a[mt][0] = __float_as_uint(av.x);
                a[mt][1] = __float_as_uint(av.y);
                a[mt][2] = __float_as_uint(av.z);
                a[mt][3] = __float_as_uint(av.w);
            }
            #pragma unroll
            for (int nt = 0; nt < 4; nt++) {
                float2 bv = *(const float2*)&Bs[kk][((wn * 4 + nt) * 32 + lane) * 2];
                b[nt][0] = __float_as_uint(bv.x);
                b[nt][1] = __float_as_uint(bv.y);
            }
            #pragma unroll
            for (int mt = 0; mt < 4; mt++)
                #pragma unroll
                for (int nt = 0; nt < 4; nt++)
                    mma_tf32(acc[mt][nt], a[mt][0], a[mt][1], a[mt][2], a[mt][3],
                             b[nt][0], b[nt][1]);
        }
        __syncthreads();
    }

    #pragma unroll
    for (int mt = 0; mt < 4; mt++) {
        int row = blockIdx.y * 128 + (wm * 4 + mt) * 16 + (lane >> 2);
        #pragma unroll
        for (int nt = 0; nt < 4; nt++) {
            int col = blockIdx.x * 128 + (wn * 4 + nt) * 8 + ((lane & 3) << 1);
            float2 bv = *(const float2*)(bias + col);
            float2 r0, r1;
            r0.x = acc[mt][nt][0] + bv.x;
            r0.y = acc[mt][nt][1] + bv.y;
            r1.x = acc[mt][nt][2] + bv.x;
            r1.y = acc[mt][nt][3] + bv.y;
            *(float2*)(C + (size_t)row * N + col)       = r0;
            *(float2*)(C + (size_t)(row + 8) * N + col) = r1;
        }
    }
}

// ---------------------------------------------------------------------------
// Tensor-core flash attention (tf32 mma, fp32 softmax/accum).
// Grid: (S/128, H, B). Block: 256 threads = 8 warps.
// Each warp owns a 16-query stripe; K-tile = 64 keys per iteration.
//
// smem (floats):
//  Qs [0,8192):      [warp][kk(8)][lane^kk][j(4)]  A-fragments, pre-scaled+tf32
//  Ks [8192,12288):  [kk(8)][np(4)][lane^kk][slot(4)]  slot={b0e,b1e,b0o,b1o}
//  Vs [12288,16384): [kk(8)][np(4)][lane^kk][slot(4)]  same for V (k=key,n=d)
// ---------------------------------------------------------------------------
#define ATT_SMEM_BYTES (16384 * 4)

__global__ __launch_bounds__(256, 2)
void attn_tc_kernel(const float* __restrict__ q, const float* __restrict__ kv,
                    const float* __restrict__ mask, float* __restrict__ outp)
{
    extern __shared__ float sm[];
    float* Qs = sm;
    float* Ks = sm + 8192;
    float* Vs = sm + 12288;

    const int tid  = threadIdx.x;
    const int lane = tid & 31;
    const int warp = tid >> 5;
    const int qt = blockIdx.x, h = blockIdx.y, b = blockIdx.z;
    const int q0 = qt * 128;

    // ---- stage Q (scaled by 1/8, tf32, A-fragment permuted) ----
    {
        const float* qbase = q + (size_t)(b * SEQ + q0) * D_MODEL + h * HEAD_DIM;
        #pragma unroll
        for (int i = 0; i < 8; i++) {
            int idx = tid + i * 256;          // 0..2047
            int row = idx >> 4;               // 0..127
            int c0  = (idx & 15) << 2;        // 0..60
            float4 v = *(const float4*)(qbase + (size_t)row * D_MODEL + c0);
            int w  = row >> 4;
            int r  = row & 15;
            int kk = c0 >> 3;
            int j  = ((r >> 3) & 1) | ((c0 & 4) ? 2 : 0);
            int l0 = (r & 7) << 2;
            int base = ((w * 8 + kk) * 32) * 4 + j;
            Qs[base + (((l0 + 0) ^ kk) << 2)] = f2tff(v.x * 0.125f);
            Qs[base + (((l0 + 1) ^ kk) << 2)] = f2tff(v.y * 0.125f);
            Qs[base + (((l0 + 2) ^ kk) << 2)] = f2tff(v.z * 0.125f);
            Qs[base + (((l0 + 3) ^ kk) << 2)] = f2tff(v.w * 0.125f);
        }
    }

    float of[8][4];
    #pragma unroll
    for (int nt = 0; nt < 8; nt++)
        #pragma unroll
        for (int r = 0; r < 4; r++) of[nt][r] = 0.0f;
    float m0 = -1e30f, m8 = -1e30f, l0s = 0.0f, l8s = 0.0f;

    const float* kvbase = kv + (size_t)(b * SEQ) * KV_DIM + h * (2 * HEAD_DIM);
    const float* mrow0  = mask + (size_t)(q0 + warp * 16 + (lane >> 2)) * SEQ
                               + ((lane & 3) << 1);

    const int srcA = (lane & 28) | ((lane & 3) >> 1);
    const int srcB = srcA | 2;
    const bool oddl = (lane & 1);

    for (int kt = 0; kt < SEQ / 64; kt++) {
        const int k0 = kt * 64;
        // ---- stage K tile (B-frag permuted, tf32) ----
        const float* kb = kvbase + (size_t)k0 * KV_DIM;
        #pragma unroll
        for (int i = 0; i < 4; i++) {
            int idx = tid + i * 256;       // 0..1023
            int kr  = idx >> 4;            // 0..63
            int c0  = (idx & 15) << 2;     // 0..60
            float4 v = *(const float4*)(kb + (size_t)kr * KV_DIM + c0);
            int kk   = c0 >> 3;
            int nt   = kr >> 3;
            int np   = nt >> 1;
            int slot = ((nt & 1) << 1) | ((c0 >> 2) & 1);
            int l0   = (kr & 7) << 2;
            int base = ((kk * 4 + np) * 32) * 4 + slot;
            Ks[base + (((l0 + 0) ^ kk) << 2)] = f2tff(v.x);
            Ks[base + (((l0 + 1) ^ kk) << 2)] = f2tff(v.y);
            Ks[base + (((l0 + 2) ^ kk) << 2)] = f2tff(v.z);
            Ks[base + (((l0 + 3) ^ kk) << 2)] = f2tff(v.w);
        }
        // ---- stage V tile (B-frag permuted: k=key, n=d) ----
        const float* vb = kb + HEAD_DIM;
        #pragma unroll
        for (int i = 0; i < 4; i++) {
            int idx = tid + i * 256;
            int kr  = idx >> 4;
            int c0  = (idx & 15) << 2;
            float4 v = *(const float4*)(vb + (size_t)kr * KV_DIM + c0);
            int kk   = kr >> 3;
            int np   = c0 >> 4;
            int slot = (((c0 >> 3) & 1) << 1) | (((kr & 7) >= 4) ? 1 : 0);
            int l0   = ((c0 & 7) << 2) + (kr & 3);
            int base = ((kk * 4 + np) * 32) * 4 + slot;
            Vs[base + (((l0 +  0) ^ kk) << 2)] = f2tff(v.x);
            Vs[base + (((l0 +  4) ^ kk) << 2)] = f2tff(v.y);
            Vs[base + (((l0 +  8) ^ kk) << 2)] = f2tff(v.z);
            Vs[base + (((l0 + 12) ^ kk) << 2)] = f2tff(v.w);
        }
        __syncthreads();

        // ---- S = Q K^T ----
        float sf[8][4];
        #pragma unroll
        for (int nt = 0; nt < 8; nt++)
            #pragma unroll
            for (int r = 0; r < 4; r++) sf[nt][r] = 0.0f;

        #pragma unroll
        for (int kk = 0; kk < 8; kk++) {
            float4 aq = *(const float4*)&Qs[((warp * 8 + kk) * 32 + (lane ^ kk)) * 4];
            unsigned a0 = __float_as_uint(aq.x), a1 = __float_as_uint(aq.y);
            unsigned a2 = __float_as_uint(aq.z), a3 = __float_as_uint(aq.w);
            #pragma unroll
            for (int np = 0; np < 4; np++) {
                float4 kf = *(const float4*)&Ks[((kk * 4 + np) * 32 + (lane ^ kk)) * 4];
                mma_tf32(sf[2 * np],     a0, a1, a2, a3,
                         __float_as_uint(kf.x), __float_as_uint(kf.y));
                mma_tf32(sf[2 * np + 1], a0, a1, a2, a3,
                         __float_as_uint(kf.z), __float_as_uint(kf.w));
            }
        }

        // ---- mask add ----
        #pragma unroll
        for (int nt = 0; nt < 8; nt++) {
            float2 mv0 = *(const float2*)(mrow0 + k0 + nt * 8);
            float2 mv8 = *(const float2*)(mrow0 + (size_t)8 * SEQ + k0 + nt * 8);
            sf[nt][0] += mv0.x; sf[nt][1] += mv0.y;
            sf[nt][2] += mv8.x; sf[nt][3] += mv8.y;
        }

        // ---- online softmax (rows r and r+8 per thread) ----
        float mx0 = -1e30f, mx8 = -1e30f;
        #pragma unroll
        for (int nt = 0; nt < 8; nt++) {
            mx0 = fmaxf(mx0, fmaxf(sf[nt][0], sf[nt][1]));
            mx8 = fmaxf(mx8, fmaxf(sf[nt][2], sf[nt][3]));
        }
        mx0 = fmaxf(mx0, __shfl_xor_sync(0xffffffffu, mx0, 1));
        mx0 = fmaxf(mx0, __shfl_xor_sync(0xffffffffu, mx0, 2));
        mx8 = fmaxf(mx8, __shfl_xor_sync(0xffffffffu, mx8, 1));
        mx8 = fmaxf(mx8, __shfl_xor_sync(0xffffffffu, mx8, 2));

        float nm0 = fmaxf(m0, mx0), nm8 = fmaxf(m8, mx8);
        float sc0 = __expf(m0 - nm0), sc8 = __expf(m8 - nm8);
        m0 = nm0; m8 = nm8;

        float rs0 = 0.0f, rs8 = 0.0f;
        #pragma unroll
        for (int nt = 0; nt < 8; nt++) {
            sf[nt][0] = __expf(sf[nt][0] - nm0); rs0 += sf[nt][0];
            sf[nt][1] = __expf(sf[nt][1] - nm0); rs0 += sf[nt][1];
            sf[nt][2] = __expf(sf[nt][2] - nm8); rs8 += sf[nt][2];
            sf[nt][3] = __expf(sf[nt][3] - nm8); rs8 += sf[nt][3];
        }
        rs0 += __shfl_xor_sync(0xffffffffu, rs0, 1);
        rs0 += __shfl_xor_sync(0xffffffffu, rs0, 2);
        rs8 += __shfl_xor_sync(0xffffffffu, rs8, 1);
        rs8 += __shfl_xor_sync(0xffffffffu, rs8, 2);
        l0s = l0s * sc0 + rs0;
        l8s = l8s * sc8 + rs8;

        #pragma unroll
        for (int nt = 0; nt < 8; nt++) {
            of[nt][0] *= sc0; of[nt][1] *= sc0;
            of[nt][2] *= sc8; of[nt][3] *= sc8;
        }

        // ---- O += P V  (P C-frag -> A-frag via shuffles) ----
        #pragma unroll
        for (int kk = 0; kk < 8; kk++) {
            float p0 = sf[kk][0], p1 = sf[kk][1], p2 = sf[kk][2], p3 = sf[kk][3];
            float e0 = __shfl_sync(0xffffffffu, p0, srcA);
            float e1 = __shfl_sync(0xffffffffu, p1, srcA);
            float e2 = __shfl_sync(0xffffffffu, p2, srcA);
            float e3 = __shfl_sync(0xffffffffu, p3, srcA);
            float g0 = __shfl_sync(0xffffffffu, p0, srcB);
            float g1 = __shfl_sync(0xffffffffu, p1, srcB);
            float g2 = __shfl_sync(0xffffffffu, p2, srcB);
            float g3 = __shfl_sync(0xffffffffu, p3, srcB);
            unsigned a0 = f2tf(oddl ? e1 : e0);
            unsigned a1 = f2tf(oddl ? e3 : e2);
            unsigned a2 = f2tf(oddl ? g1 : g0);
            unsigned a3 = f2tf(oddl ? g3 : g2);
            #pragma unroll
            for (int np = 0; np < 4; np++) {
                float4 vf = *(const float4*)&Vs[((kk * 4 + np) * 32 + (lane ^ kk)) * 4];
                mma_tf32(of[2 * np],     a0, a1, a2, a3,
                         __float_as_uint(vf.x), __float_as_uint(vf.y));
                mma_tf32(of[2 * np + 1], a0, a1, a2, a3,
                         __float_as_uint(vf.z), __float_as_uint(vf.w));
            }
        }
        __syncthreads();
    }

    // ---- normalize + store ----
    float inv0 = 1.0f / l0s, inv8 = 1.0f / l8s;
    float* obase = outp + (size_t)(b * SEQ + q0 + warp * 16 + (lane >> 2)) * D_MODEL
                        + h * HEAD_DIM + ((lane & 3) << 1);
    #pragma unroll
    for (int nt = 0; nt < 8; nt++) {
        float2 r0 = make_float2(of[nt][0] * inv0, of[nt][1] * inv0);
        float2 r8 = make_float2(of[nt][2] * inv8, of[nt][3] * inv8);
        *(float2*)(obase + nt * 8)                      = r0;
        *(float2*)(obase + (size_t)8 * D_MODEL + nt * 8) = r8;
    }
}

// ---------------------------------------------------------------------------
extern "C" void kernel_launch(void* const* d_in, const int* in_sizes, int n_in,
                              void* d_out, int out_size)
{
    const float* x    = (const float*)d_in[0];
    const float* y    = (const float*)d_in[1];
    const float* mask = (const float*)d_in[2];
    const float* Wq   = (const float*)d_in[3];
    const float* bq   = (const float*)d_in[4];
    const float* Wkv  = (const float*)d_in[5];
    const float* bkv  = (const float*)d_in[6];
    const float* Wo   = (const float*)d_in[7];
    const float* bo   = (const float*)d_in[8];
    float* out = (float*)d_out;

    float *qp, *kvp, *attnp;
    cudaGetSymbolAddress((void**)&qp,    g_q);
    cudaGetSymbolAddress((void**)&kvp,   g_kv);
    cudaGetSymbolAddress((void**)&attnp, g_attn);

    cudaFuncSetAttribute(attn_tc_kernel,
                         cudaFuncAttributeMaxDynamicSharedMemorySize,
                         ATT_SMEM_BYTES);

    dim3 blk(256);

    gemm_tf32_kernel<<<dim3(D_MODEL / 128, M_TOT / 128), blk>>>(
        x, Wq, bq, qp, M_TOT, D_MODEL, D_MODEL);
    gemm_tf32_kernel<<<dim3(KV_DIM / 128, M_TOT / 128), blk>>>(
        y, Wkv, bkv, kvp, M_TOT, KV_DIM, D_MODEL);
    attn_tc_kernel<<<dim3(SEQ / 128, NUM_HEADS, BATCH), blk, ATT_SMEM_BYTES>>>(
        qp, kvp, mask, attnp);
    gemm_tf32_kernel<<<dim3(D_MODEL / 128, M_TOT / 128), blk>>>(
        attnp, Wo, bo, out, M_TOT, D_MODEL, D_MODEL);
}